// round 2
// baseline (speedup 1.0000x reference)
#include <cuda_runtime.h>
#include <stdint.h>

#define BOX 120
#define BOX3 1728000            // 120^3
#define MAXA 512
#define BT_C 44                 // BATCH(4) * NUM_TYPES(11)
#define PAIRS 25                // 5x5 (ox,oy) offsets

#define NCHUNK 11               // chunks of the bt dimension
#define BTPC 4                  // bt per chunk (44/11)
#define NZ 1024                 // zeroing blocks
#define NS 160                  // scatter blocks
#define NBLK (NZ + NS)
#define THREADS 256

#define CHUNK_F4 (BTPC * BOX3 / 4)        // 1,728,000 float4 per chunk
#define PAIRS_PER_CHUNK (BTPC * MAXA * PAIRS)  // 51,200

// Cross-block pipeline state (zero-initialized at module load; reset at the
// end of every kernel run so each call — eager, captured, or replayed —
// starts from the same state).
__device__ int g_cnt[NCHUNK];
__device__ int g_ack;

__device__ __forceinline__ int ld_cg(const int* p) {
    int v;
    asm volatile("ld.global.cg.b32 %0, [%1];" : "=r"(v) : "l"(p));
    return v;
}

__device__ __forceinline__ void scatter_pair(const float* __restrict__ coords,
                                             const void* __restrict__ natoms_raw,
                                             float* __restrict__ out,
                                             int bt, int a, int pair) {
    // num_atoms may arrive as int64 or int32 (jax x64 flag). Probe element 0:
    // an int32-packed buffer viewed as int64 has n[1]>=1 in the high word,
    // so the value lands far outside [1, MAXA].
    const long long* n64 = (const long long*)natoms_raw;
    const int*       n32 = (const int*)natoms_raw;
    long long probe = n64[0];
    int n = (probe >= 1 && probe <= MAXA) ? (int)n64[bt] : n32[bt];
    if (a >= n) return;

    const float* c3 = coords + (long long)bt * (3 * MAXA) + 3 * a;
    float x = c3[0], y = c3[1], z = c3[2];
    int cx = (int)floorf(x);
    int cy = (int)floorf(y);
    int cz = (int)floorf(z);

    int gx = cx + pair / 5 - 2;
    int gy = cy + pair % 5 - 2;
    if ((unsigned)gx >= BOX || (unsigned)gy >= BOX) return;

    float dx = (float)gx - x;
    float dy = (float)gy - y;
    float wxy = __expf(-(dx * dx + dy * dy));

    float* base = out + (long long)bt * BOX3 + ((long long)gx * BOX + gy) * BOX;
    #pragma unroll
    for (int oz = -2; oz <= 2; ++oz) {
        int gz = cz + oz;
        if ((unsigned)gz < BOX) {
            float dz = (float)gz - z;
            atomicAdd(base + gz, wxy * __expf(-dz * dz));   // compiles to REDG
        }
    }
}

__global__ void __launch_bounds__(THREADS, 8)
fused_kernel(const float* __restrict__ coords,
             const void* __restrict__ natoms_raw,
             float* __restrict__ out) {
    int bid = blockIdx.x;
    int tid = threadIdx.x;

    if (bid < NZ) {
        // ---------------- zero role: stream zeros chunk by chunk ----------
        float4 zero4 = make_float4(0.f, 0.f, 0.f, 0.f);
        float4* out4 = (float4*)out;
        for (int c = 0; c < NCHUNK; ++c) {
            float4* p = out4 + (size_t)c * CHUNK_F4;
            for (int i = bid * THREADS + tid; i < CHUNK_F4; i += NZ * THREADS)
                p[i] = zero4;
            __threadfence();        // release: stores visible before counter bump
            __syncthreads();
            if (tid == 0) atomicAdd(&g_cnt[c], 1);
        }
    } else {
        // ---------------- scatter role: consume chunks as they complete ---
        int sb = bid - NZ;
        for (int c = 0; c < NCHUNK; ++c) {
            if (tid == 0) {
                while (ld_cg(&g_cnt[c]) < NZ) __nanosleep(100);
            }
            __syncthreads();
            __threadfence();        // acquire
            for (int p = sb * THREADS + tid; p < PAIRS_PER_CHUNK; p += NS * THREADS) {
                int pair = p % PAIRS;
                int rest = p / PAIRS;
                int a    = rest % MAXA;
                int btl  = rest / MAXA;
                scatter_pair(coords, natoms_raw, out, c * BTPC + btl, a, pair);
            }
        }
        // -------- ack + state reset so the next call starts clean ---------
        __threadfence();
        __syncthreads();
        if (tid == 0) atomicAdd(&g_ack, 1);
        if (sb == 0 && tid == 0) {
            while (ld_cg(&g_ack) < NS) __nanosleep(100);
            // All scatter blocks have passed every spin; all zero blocks are
            // done incrementing. Safe to reset.
            #pragma unroll
            for (int c = 0; c < NCHUNK; ++c) g_cnt[c] = 0;
            __threadfence();
            g_ack = 0;
            __threadfence();
        }
    }
}

extern "C" void kernel_launch(void* const* d_in, const int* in_sizes, int n_in,
                              void* d_out, int out_size) {
    const float* coords = (const float*)d_in[0];
    const void*  natoms = d_in[1];
    float* out = (float*)d_out;
    fused_kernel<<<NBLK, THREADS>>>(coords, natoms, out);
}

// round 3
// speedup vs baseline: 1.3587x; 1.3587x over previous
#include <cuda_runtime.h>
#include <stdint.h>

#define BOX 120
#define BOX3 1728000            // 120^3
#define MAXA 512
#define BT_C 44                 // BATCH(4) * NUM_TYPES(11)
#define THREADS 256
#define NBUCK 24                // cy coarse buckets (width 5)
#define BCAP 32                 // atoms per bucket cap (mean ~0.9, P(>32) ~ 1e-40)
#define ROW_F4 30               // 120 / 4 float4 per z-row
#define PLANE_F4 (120 * ROW_F4) // 3600 float4 per (bt,gx) plane

// One block per (bt, gx) plane. Gather formulation: each voxel computes its
// final value from nearby atoms, so the 304MB output is written exactly once
// (no zero pass, no atomics, no cross-block sync).
__global__ void __launch_bounds__(THREADS, 8)
gather_kernel(const float* __restrict__ coords,
              const void* __restrict__ natoms_raw,
              float* __restrict__ out) {
    const int bx = blockIdx.x;
    const int bt = bx / BOX;
    const int gx = bx - bt * BOX;
    const int tid = threadIdx.x;

    __shared__ int    s_cnt[NBUCK];
    __shared__ float4 s_rec[NBUCK][BCAP];   // {ay, az, wx, pack(cy,cz)}

    if (tid < NBUCK) s_cnt[tid] = 0;
    __syncthreads();

    // num_atoms may be int64 or int32 (jax x64 flag). Probe element 0: an
    // int32-packed buffer viewed as int64 carries n[1]>=1 in the high word,
    // putting the value far outside [1, MAXA].
    const long long* n64 = (const long long*)natoms_raw;
    const int*       n32 = (const int*)natoms_raw;
    long long probe = n64[0];
    int n = (probe >= 1 && probe <= MAXA) ? (int)n64[bt] : n32[bt];

    // ---- Phase 1: collect atoms whose home-cell x is within gx +/- 2 ----
    const float* cbase = coords + (long long)bt * (3 * MAXA);
    float fgx = (float)gx;
    for (int a = tid; a < n; a += THREADS) {
        float ax = cbase[3 * a + 0];
        int cx = (int)floorf(ax);
        if ((unsigned)(gx - cx + 2) > 4u) continue;       // cell-window on x
        float ay = cbase[3 * a + 1];
        float az = cbase[3 * a + 2];
        int cy = (int)floorf(ay);
        int cz = (int)floorf(az);
        float dx = fgx - ax;
        float wx = __expf(-dx * dx);
        int b = cy / 5;                                    // cy in [0,119]
        int slot = atomicAdd(&s_cnt[b], 1);
        if (slot < BCAP) {
            s_rec[b][slot] = make_float4(ay, az, wx,
                                         __int_as_float(cy | (cz << 16)));
        }
    }
    __syncthreads();

    // ---- Phase 2: one float4 (4 z-voxels) per thread per iteration ----
    float* obase = out + (long long)bt * BOX3 + (long long)gx * (BOX * BOX);
    for (int i = tid; i < PLANE_F4; i += THREADS) {
        int gy = i / ROW_F4;
        int q  = i - gy * ROW_F4;
        int z0 = q * 4;

        float v0 = 0.f, v1 = 0.f, v2 = 0.f, v3 = 0.f;
        float fgy = (float)gy;
        float fz0 = (float)z0;

        int b0 = (gy >= 2 ? gy - 2 : 0) / 5;
        int b1 = (gy <= 117 ? gy + 2 : 119) / 5;
        for (int b = b0; b <= b1; ++b) {
            int cnt = min(s_cnt[b], BCAP);
            for (int j = 0; j < cnt; ++j) {
                float4 r = s_rec[b][j];
                int cyz = __float_as_int(r.w);
                int cy = cyz & 0xffff;
                if ((unsigned)(gy - cy + 2) > 4u) continue;   // y window
                int cz = cyz >> 16;
                float dy = fgy - r.x;
                float wxy = r.z * __expf(-dy * dy);
                // z window for the 4 voxels z0..z0+3
                float dz0 = fz0 - r.y;
                if ((unsigned)(z0 + 0 - cz + 2) <= 4u) v0 += wxy * __expf(-dz0 * dz0);
                float dz1 = dz0 + 1.f;
                if ((unsigned)(z0 + 1 - cz + 2) <= 4u) v1 += wxy * __expf(-dz1 * dz1);
                float dz2 = dz0 + 2.f;
                if ((unsigned)(z0 + 2 - cz + 2) <= 4u) v2 += wxy * __expf(-dz2 * dz2);
                float dz3 = dz0 + 3.f;
                if ((unsigned)(z0 + 3 - cz + 2) <= 4u) v3 += wxy * __expf(-dz3 * dz3);
            }
        }
        ((float4*)(obase + gy * BOX))[q] = make_float4(v0, v1, v2, v3);
    }
}

extern "C" void kernel_launch(void* const* d_in, const int* in_sizes, int n_in,
                              void* d_out, int out_size) {
    const float* coords = (const float*)d_in[0];
    const void*  natoms = d_in[1];
    float* out = (float*)d_out;
    gather_kernel<<<BT_C * BOX, THREADS>>>(coords, natoms, out);
}

// round 5
// speedup vs baseline: 1.9107x; 1.4063x over previous
#include <cuda_runtime.h>
#include <stdint.h>

#define BOX 120
#define BOX3 1728000            // 120^3
#define MAXA 512
#define BT_C 44                 // BATCH(4) * NUM_TYPES(11)
#define THREADS 256
#define HROWS 60                // gy rows per block (half plane)
#define HALF_F4 (HROWS * BOX / 4)   // 1800 float4 per half-plane
#define RCAP 128                // atom records per block (mean ~11)

// Block = (bt, gx, half). SMEM plane accumulator:
//   A) zero smem plane + collect nearby atoms
//   B) scatter atoms into smem plane (shared atomics, ~11 atoms * <=25 cells)
//   C) linear smem -> gmem float4 stream (half-plane is contiguous in both)
__global__ void __launch_bounds__(THREADS)
plane_kernel(const float* __restrict__ coords,
             const void* __restrict__ natoms_raw,
             float* __restrict__ out) {
    __shared__ float  s_plane[HROWS * BOX];     // 28.8 KB
    __shared__ float4 s_rec[RCAP];              // {ay, az, wx, pack(cy,cz)}
    __shared__ int    s_cnt;

    const int b    = blockIdx.x;
    const int bt   = b / (BOX * 2);
    const int rem  = b - bt * (BOX * 2);
    const int gx   = rem >> 1;
    const int gy0  = (rem & 1) * HROWS;
    const int tid  = threadIdx.x;

    if (tid == 0) s_cnt = 0;
    __syncthreads();

    // ---- Phase A: zero plane + collect atoms ----
    float4* sp4 = (float4*)s_plane;
    #pragma unroll 4
    for (int i = tid; i < HALF_F4; i += THREADS)
        sp4[i] = make_float4(0.f, 0.f, 0.f, 0.f);

    // num_atoms may be int64 or int32 (jax x64 flag). Probe element 0: an
    // int32-packed buffer viewed as int64 carries n[1]>=1 in the high word,
    // far outside [1, MAXA].
    const long long* n64 = (const long long*)natoms_raw;
    const int*       n32 = (const int*)natoms_raw;
    long long probe = n64[0];
    int n = (probe >= 1 && probe <= MAXA) ? (int)n64[bt] : n32[bt];

    const float* cbase = coords + (long long)bt * (3 * MAXA);
    float fgx = (float)gx;
    for (int a = tid; a < n; a += THREADS) {
        float ax = cbase[3 * a + 0];
        int cx = (int)floorf(ax);
        if ((unsigned)(gx - cx + 2) > 4u) continue;        // x cell-window
        float ay = cbase[3 * a + 1];
        int cy = (int)floorf(ay);
        if (cy < gy0 - 2 || cy > gy0 + HROWS + 1) continue; // y reach of half
        float az = cbase[3 * a + 2];
        int cz = (int)floorf(az);
        float dx = fgx - ax;
        float wx = __expf(-dx * dx);
        int slot = atomicAdd(&s_cnt, 1);
        if (slot < RCAP)
            s_rec[slot] = make_float4(ay, az, wx,
                                      __int_as_float((cy & 0xffff) | (cz << 16)));
    }
    __syncthreads();

    // ---- Phase B: scatter atoms into smem plane ----
    int cnt = min(s_cnt, RCAP);
    for (int idx = tid; idx < cnt; idx += THREADS) {
        float4 r = s_rec[idx];
        int cyz = __float_as_int(r.w);
        int cy = (int)(short)(cyz & 0xffff);
        int cz = cyz >> 16;
        float wx = r.z;

        float ey[5]; int gyv[5];
        float ez[5]; int gzv[5];
        #pragma unroll
        for (int j = 0; j < 5; ++j) {
            int gy = cy + j - 2;
            gyv[j] = (gy >= gy0 && gy < gy0 + HROWS && gy < BOX && gy >= 0) ? gy - gy0 : -1;
            float dy = (float)gy - r.x;
            ey[j] = __expf(-dy * dy);
            int gz = cz + j - 2;
            gzv[j] = ((unsigned)gz < BOX) ? gz : -1;
            float dz = (float)gz - r.y;
            ez[j] = __expf(-dz * dz);
        }
        #pragma unroll
        for (int j = 0; j < 5; ++j) {
            if (gyv[j] < 0) continue;
            float wxy = wx * ey[j];
            float* row = s_plane + gyv[j] * BOX;
            #pragma unroll
            for (int k = 0; k < 5; ++k) {
                if (gzv[k] >= 0)
                    atomicAdd(row + gzv[k], wxy * ez[k]);
            }
        }
    }
    __syncthreads();

    // ---- Phase C: linear smem -> gmem stream ----
    float4* dst4 = (float4*)(out + (long long)bt * BOX3
                                 + (long long)gx * (BOX * BOX)
                                 + gy0 * BOX);
    #pragma unroll 4
    for (int i = tid; i < HALF_F4; i += THREADS) {
        float4 v = sp4[i];
        __stcs(dst4 + i, v);
    }
}

extern "C" void kernel_launch(void* const* d_in, const int* in_sizes, int n_in,
                              void* d_out, int out_size) {
    const float* coords = (const float*)d_in[0];
    const void*  natoms = d_in[1];
    float* out = (float*)d_out;
    plane_kernel<<<BT_C * BOX * 2, THREADS>>>(coords, natoms, out);
}